// round 2
// baseline (speedup 1.0000x reference)
#include <cuda_runtime.h>
#include <cstdint>

// Problem dims
#define B_DIM 32
#define S_DIM 2048
#define H_DIM 1024
#define NROWS (B_DIM * S_DIM)   // 65536

// ---------------- device scratch (no allocs allowed) ----------------
__device__ float g_scores[B_DIM * S_DIM];          // pre-softmax scores
__device__ float g_c[B_DIM * H_DIM];               // hW[b,k] + attn_b[k]
__device__ float g_WeT[H_DIM * H_DIM];             // We^T: [h][k], tf32-rounded

// ---------------- helpers ----------------
__device__ __forceinline__ uint32_t smem_u32(const void* p) {
    uint32_t a;
    asm("{ .reg .u64 t; cvta.to.shared.u64 t, %1; cvt.u32.u64 %0, t; }"
        : "=r"(a) : "l"(p));
    return a;
}

__device__ __forceinline__ uint32_t f2tf32(float f) {
    uint32_t u;
    asm("cvt.rna.tf32.f32 %0, %1;" : "=r"(u) : "f"(f));
    return u;
}

// accurate-enough tanh from MUFU ex2 + rcp (~1e-6 rel err)
__device__ __forceinline__ float tanh_acc(float x) {
    float e;
    asm("ex2.approx.f32 %0, %1;" : "=f"(e) : "f"(x * 2.885390081777927f)); // 2*log2(e)
    float r;
    asm("rcp.approx.f32 %0, %1;" : "=f"(r) : "f"(e + 1.0f));
    return fmaf(-2.0f, r, 1.0f);
}

#define CP_ASYNC16(dst_u32, src_ptr) \
    asm volatile("cp.async.cg.shared.global [%0], [%1], 16;" \
                 :: "r"(dst_u32), "l"(src_ptr) : "memory")
#define CP_ASYNC_COMMIT() asm volatile("cp.async.commit_group;" ::: "memory")
#define CP_ASYNC_WAIT1()  asm volatile("cp.async.wait_group 1;" ::: "memory")
#define CP_ASYNC_WAIT0()  asm volatile("cp.async.wait_group 0;" ::: "memory")

__device__ __forceinline__ void mma_tf32(float d[4], const uint32_t a[4],
                                         const uint32_t b[2]) {
    asm volatile(
        "mma.sync.aligned.m16n8k8.row.col.f32.tf32.tf32.f32 "
        "{%0,%1,%2,%3}, {%4,%5,%6,%7}, {%8,%9}, {%0,%1,%2,%3};"
        : "+f"(d[0]), "+f"(d[1]), "+f"(d[2]), "+f"(d[3])
        : "r"(a[0]), "r"(a[1]), "r"(a[2]), "r"(a[3]), "r"(b[0]), "r"(b[1]));
}

// ---------------- kernel A: transpose + tf32-round We ----------------
// g_WeT[h][n] = rna_tf32(attn_w[n][H + h])
__global__ void transpose_we_kernel(const float* __restrict__ attn_w) {
    __shared__ float t[32][33];
    int nb = blockIdx.x * 32, hb = blockIdx.y * 32;
    int x = threadIdx.x, y = threadIdx.y;   // 32 x 8
    #pragma unroll
    for (int j = 0; j < 4; j++)
        t[y + 8 * j][x] = attn_w[(size_t)(nb + y + 8 * j) * (2 * H_DIM) + H_DIM + hb + x];
    __syncthreads();
    #pragma unroll
    for (int j = 0; j < 4; j++)
        g_WeT[(size_t)(hb + y + 8 * j) * H_DIM + nb + x] =
            __uint_as_float(f2tf32(t[x][y + 8 * j]));
}

// ---------------- kernel 0: init output + zero scores ----------------
__global__ void init_kernel(const float* __restrict__ hidden, float* __restrict__ out) {
    int idx = blockIdx.x * 256 + threadIdx.x;          // 0..65535
    int b = idx >> 11;
    int c = idx & 2047;
    out[idx] = (c < H_DIM) ? 0.0f : hidden[b * H_DIM + (c - H_DIM)];
    g_scores[idx] = 0.0f;
}

// ---------------- kernel 1: c[b,k] = hidden @ Wh^T + attn_b ----------------
__global__ void cvec_kernel(const float* __restrict__ hidden,
                            const float* __restrict__ attn_w,
                            const float* __restrict__ attn_b) {
    int b = blockIdx.x;
    int wid = threadIdx.x >> 5, lane = threadIdx.x & 31;
    int k = blockIdx.y * 8 + wid;
    const float* hrow = hidden + b * H_DIM;
    const float* wrow = attn_w + (size_t)k * (2 * H_DIM);   // Wh row k
    float s = 0.0f;
    #pragma unroll 8
    for (int h = lane; h < H_DIM; h += 32) s += hrow[h] * wrow[h];
    #pragma unroll
    for (int o = 16; o > 0; o >>= 1) s += __shfl_xor_sync(0xffffffffu, s, o);
    if (lane == 0) g_c[b * H_DIM + k] = s + attn_b[k];
}

// ---------------- kernel 2: fused tf32 mma.sync GEMM + tanh + v-dot ----------------
// CTA tile: M=128 rows x N=256 features, K=1024 (32 iters of KC=32).
// 8 warps as 2(m) x 4(n), warp tile 64x64 via m16n8k8.
static constexpr int NKITER = 32;
// smem word layout (floats):
//   c_sm  [0, 256)
//   v_sm  [256, 512)
//   A0    [512, 512+4096)          128 x 32, word = m*32 + (k ^ 4*(m&7))
//   A1    [4608, 8704)
//   B0    [8704, 8704+8192)        32 x 256, word = k*256 + (n ^ 8*(k&3))
//   B1    [16896, 25088)
static constexpr int W_C  = 0;
static constexpr int W_V  = 256;
static constexpr int W_A0 = 512;
static constexpr int W_A1 = W_A0 + 4096;
static constexpr int W_B0 = W_A1 + 4096;
static constexpr int W_B1 = W_B0 + 8192;
static constexpr int GEMM_SMEM_BYTES = (W_B1 + 8192) * 4;   // 100,352

__device__ __forceinline__ void load_tiles(uint32_t smem_base, int bufA_w, int bufB_w,
                                           const float* __restrict__ enc,
                                           int row0, int kg0, int it, int tid) {
    const int hbase = it * 32;
    // A: 128 rows x 32 words = 1024 16B chunks
    #pragma unroll
    for (int j = 0; j < 4; j++) {
        int c = tid + j * 256;
        int m = c >> 3, k0 = (c & 7) * 4;
        uint32_t w = (uint32_t)(bufA_w + m * 32 + (k0 ^ ((m & 7) * 4)));
        CP_ASYNC16(smem_base + w * 4, enc + (size_t)(row0 + m) * H_DIM + hbase + k0);
    }
    // B: 32 rows(k) x 256 words = 2048 16B chunks
    #pragma unroll
    for (int j = 0; j < 8; j++) {
        int c = tid + j * 256;
        int k = c >> 6, n0 = (c & 63) * 4;
        uint32_t w = (uint32_t)(bufB_w + k * 256 + (n0 ^ ((k & 3) * 8)));
        CP_ASYNC16(smem_base + w * 4, g_WeT + (size_t)(hbase + k) * H_DIM + kg0 + n0);
    }
}

__global__ void __launch_bounds__(256, 1)
gemm_scores_kernel(const float* __restrict__ enc,
                   const float* __restrict__ v_w) {
    extern __shared__ float smw[];
    uint32_t smem_base = smem_u32(smw);
    const int tid = threadIdx.x;
    const int wid = tid >> 5, lane = tid & 31;
    const int q = lane >> 2, t4 = lane & 3;
    const int wm = wid & 1, wn = wid >> 1;          // 2 x 4 warp grid
    const int row0 = blockIdx.x * 128;
    const int b = row0 >> 11;
    const int kg0 = blockIdx.y * 256;

    // epilogue vectors
    smw[W_C + tid] = g_c[b * H_DIM + kg0 + tid];
    smw[W_V + tid] = v_w[kg0 + tid];

    // accumulators: 4 m-tiles x 8 n-tiles x 4 regs
    float d[4][8][4];
    #pragma unroll
    for (int mt = 0; mt < 4; mt++)
        #pragma unroll
        for (int nt = 0; nt < 8; nt++)
            #pragma unroll
            for (int r = 0; r < 4; r++) d[mt][nt][r] = 0.0f;

    // prologue
    load_tiles(smem_base, W_A0, W_B0, enc, row0, kg0, 0, tid);
    CP_ASYNC_COMMIT();
    load_tiles(smem_base, W_A1, W_B1, enc, row0, kg0, 1, tid);
    CP_ASYNC_COMMIT();

    for (int it = 0; it < NKITER; it++) {
        const int bufA = (it & 1) ? W_A1 : W_A0;
        const int bufB = (it & 1) ? W_B1 : W_B0;
        CP_ASYNC_WAIT1();
        __syncthreads();

        #pragma unroll
        for (int ks = 0; ks < 4; ks++) {
            const int k0 = ks * 8;
            uint32_t a[4][4];
            uint32_t bb[8][2];
            #pragma unroll
            for (int mt = 0; mt < 4; mt++) {
                int ms = wm * 64 + mt * 16 + q;
                int base = bufA + ms * 32;
                int sw = (ms & 7) * 4;
                int k = k0 + t4;
                a[mt][0] = f2tf32(smw[base + (k ^ sw)]);
                a[mt][1] = f2tf32(smw[base + 256 + (k ^ sw)]);
                a[mt][2] = f2tf32(smw[base + ((k + 4) ^ sw)]);
                a[mt][3] = f2tf32(smw[base + 256 + ((k + 4) ^ sw)]);
            }
            #pragma unroll
            for (int nt = 0; nt < 8; nt++) {
                int n = wn * 64 + nt * 8 + q;
                int k = k0 + t4;
                int sw = (k & 3) * 8;
                bb[nt][0] = __float_as_uint(smw[bufB + k * 256 + (n ^ sw)]);
                bb[nt][1] = __float_as_uint(smw[bufB + (k + 4) * 256 + (n ^ sw)]);
            }
            #pragma unroll
            for (int mt = 0; mt < 4; mt++)
                #pragma unroll
                for (int nt = 0; nt < 8; nt++)
                    mma_tf32(d[mt][nt], a[mt], bb[nt]);
        }

        __syncthreads();
        if (it + 2 < NKITER)
            load_tiles(smem_base, bufA, bufB, enc, row0, kg0, it + 2, tid);
        CP_ASYNC_COMMIT();
    }
    CP_ASYNC_WAIT0();

    // Epilogue: score[r] += sum_n v[n] * tanh(d + c[n])
    #pragma unroll
    for (int mt = 0; mt < 4; mt++) {
        float s0 = 0.0f, s1 = 0.0f;
        #pragma unroll
        for (int nt = 0; nt < 8; nt++) {
            int n = wn * 64 + nt * 8 + t4 * 2;
            float c0 = smw[W_C + n], c1 = smw[W_C + n + 1];
            float v0 = smw[W_V + n], v1 = smw[W_V + n + 1];
            s0 = fmaf(tanh_acc(d[mt][nt][0] + c0), v0, s0);
            s0 = fmaf(tanh_acc(d[mt][nt][1] + c1), v1, s0);
            s1 = fmaf(tanh_acc(d[mt][nt][2] + c0), v0, s1);
            s1 = fmaf(tanh_acc(d[mt][nt][3] + c1), v1, s1);
        }
        // reduce across the 4 lanes of each quad (cols)
        #pragma unroll
        for (int o = 1; o < 4; o <<= 1) {
            s0 += __shfl_xor_sync(0xffffffffu, s0, o);
            s1 += __shfl_xor_sync(0xffffffffu, s1, o);
        }
        if (t4 == 0) {
            int r = row0 + wm * 64 + mt * 16 + q;
            atomicAdd(&g_scores[r], s0);
            atomicAdd(&g_scores[r + 8], s1);
        }
    }
}

// ---------------- kernel 3: softmax over S per batch ----------------
__global__ void softmax_kernel(float* __restrict__ outw) {
    __shared__ float sh[S_DIM];
    __shared__ float red[256];
    int b = blockIdx.x, tid = threadIdx.x;
    float lmax = -1e30f;
    for (int i = tid; i < S_DIM; i += 256) {
        float v = g_scores[b * S_DIM + i];
        sh[i] = v;
        lmax = fmaxf(lmax, v);
    }
    red[tid] = lmax;
    __syncthreads();
    for (int s = 128; s > 0; s >>= 1) {
        if (tid < s) red[tid] = fmaxf(red[tid], red[tid + s]);
        __syncthreads();
    }
    float m = red[0];
    __syncthreads();
    float lsum = 0.0f;
    for (int i = tid; i < S_DIM; i += 256) {
        float e = expf(sh[i] - m);
        sh[i] = e;
        lsum += e;
    }
    red[tid] = lsum;
    __syncthreads();
    for (int s = 128; s > 0; s >>= 1) {
        if (tid < s) red[tid] += red[tid + s];
        __syncthreads();
    }
    float inv = 1.0f / red[0];
    for (int i = tid; i < S_DIM; i += 256) outw[b * S_DIM + i] = sh[i] * inv;
}

// ---------------- kernel 4: context[b,h] = sum_s w[b,s] * enc[b,s,h] ----------------
__global__ void context_kernel(const float* __restrict__ enc,
                               const float* __restrict__ w,
                               float* __restrict__ out) {
    __shared__ float ws[128];
    int b = blockIdx.x, sc = blockIdx.y, tid = threadIdx.x;
    if (tid < 128) ws[tid] = w[b * S_DIM + sc * 128 + tid];
    __syncthreads();
    const float4* e4 = reinterpret_cast<const float4*>(
        enc + ((size_t)(b * S_DIM + sc * 128)) * H_DIM);
    float ax = 0.f, ay = 0.f, az = 0.f, aw = 0.f;
    #pragma unroll 4
    for (int s = 0; s < 128; s++) {
        float wv = ws[s];
        float4 ev = e4[(size_t)s * 256 + tid];
        ax += wv * ev.x; ay += wv * ev.y; az += wv * ev.z; aw += wv * ev.w;
    }
    float* o = out + b * (2 * H_DIM) + tid * 4;
    atomicAdd(o + 0, ax);
    atomicAdd(o + 1, ay);
    atomicAdd(o + 2, az);
    atomicAdd(o + 3, aw);
}

// ---------------- launcher ----------------
extern "C" void kernel_launch(void* const* d_in, const int* in_sizes, int n_in,
                              void* d_out, int out_size) {
    const float* hidden = (const float*)d_in[0];   // (32, 1024)
    const float* enc    = (const float*)d_in[1];   // (32, 2048, 1024)
    const float* attn_w = (const float*)d_in[2];   // (1024, 2048)
    const float* attn_b = (const float*)d_in[3];   // (1024,)
    const float* v_w    = (const float*)d_in[4];   // (1, 1024)
    float* out = (float*)d_out;                    // [output (32,2048) | attn_w (32,2048,1)]

    cudaFuncSetAttribute(gemm_scores_kernel,
                         cudaFuncAttributeMaxDynamicSharedMemorySize,
                         GEMM_SMEM_BYTES);

    transpose_we_kernel<<<dim3(32, 32), dim3(32, 8)>>>(attn_w);
    init_kernel<<<256, 256>>>(hidden, out);
    cvec_kernel<<<dim3(32, 128), 256>>>(hidden, attn_w, attn_b);
    gemm_scores_kernel<<<dim3(512, 4), 256, GEMM_SMEM_BYTES>>>(enc, v_w);
    softmax_kernel<<<32, 256>>>(out + B_DIM * S_DIM);
    context_kernel<<<dim3(32, 16), 256>>>(enc, out + B_DIM * S_DIM, out);
}